// round 9
// baseline (speedup 1.0000x reference)
#include <cuda_runtime.h>
#include <math.h>
#include <stdint.h>

#define BATCH  64
#define TOKENS 4096
#define SLOTS  64
#define ADIM   32
#define EDIM   64
#define TILE_T 128
#define NCHUNK 8
#define BPB    4      // blocks per batch; BPB*NCHUNK*TILE_T == TOKENS

// padded strides (floats): all ≡ 4 (mod 32) and 16B-multiples -> ldmatrix conflict-free
#define PT 132
#define PQ 36
#define PW 68

// shared float offsets (main phase)
#define O_XTS 0                      // [64 d][PT]  x^T tf32 (XOR-swizzled chunks)
#define O_WWS (O_XTS + 64 * PT)      // [64 s][PT]  ww^T tf32 (linear)
#define O_QS  (O_WWS + 64 * PT)      // [128 t][PQ] qhat tf32
#define O_WQS (O_QS  + 128 * PQ)     // [48 a][PW]  Wq 0-31, Wg 32, 33-47 zero
#define O_AS  (O_WQS + 48 * PW)      // [64 s][PQ]  4*ahat tf32
#define SM_FLOATS (O_AS + 64 * PQ)
#define SM_BYTES  (SM_FLOATS * 4)    // 108288 B -> 2 CTAs/SM

// finalize-phase smem reuse (stride 68 => float4-aligned rows)
#define F_PT  0                      // Pt[d][s]  64 x 68
#define F_WV  (F_PT + 64 * 68)       // WvT[d][e] 64 x 68
#define F_WS  (F_WV + 64 * 68)       // [64] W sums

__device__ float g_Ppart[BPB * BATCH * SLOTS * EDIM];   // [bx][b][s][e]
__device__ float g_Wpart[BPB * BATCH * SLOTS];
__device__ int   g_cnt[BATCH];                          // zero-init; self-resetting

__device__ __forceinline__ float tf32r(float f) {
    uint32_t u; asm("cvt.rna.tf32.f32 %0, %1;" : "=r"(u) : "f"(f));
    return __uint_as_float(u);
}
__device__ __forceinline__ void mma8(float* c, uint32_t a0, uint32_t a1,
                                     uint32_t a2, uint32_t a3,
                                     uint32_t b0, uint32_t b1) {
    asm volatile("mma.sync.aligned.m16n8k8.row.col.f32.tf32.tf32.f32 "
        "{%0,%1,%2,%3}, {%4,%5,%6,%7}, {%8,%9}, {%0,%1,%2,%3};"
        : "+f"(c[0]), "+f"(c[1]), "+f"(c[2]), "+f"(c[3])
        : "r"(a0), "r"(a1), "r"(a2), "r"(a3), "r"(b0), "r"(b1));
}
__device__ __forceinline__ void ldm4(uint32_t* r, uint32_t a) {
    asm volatile("ldmatrix.sync.aligned.m8n8.x4.shared.b16 {%0,%1,%2,%3}, [%4];"
        : "=r"(r[0]), "=r"(r[1]), "=r"(r[2]), "=r"(r[3]) : "r"(a));
}
__device__ __forceinline__ uint32_t smem_u32(const void* p) {
    uint32_t a;
    asm("{ .reg .u64 t; cvta.to.shared.u64 t, %1; cvt.u32.u64 %0, t; }" : "=r"(a) : "l"(p));
    return a;
}
// XTS swizzled float index: row d, element t
__device__ __forceinline__ int xidx(int d, int t) {
    return O_XTS + d * PT + ((((t >> 2) ^ ((d >> 2) & 7)) << 2) | (t & 3));
}
#define U(x) __float_as_uint(x)

// ============================================================
// single fused kernel: grid (BPB, BATCH), 256 threads
// ============================================================
__global__ __launch_bounds__(256, 2)
void main_kernel(const float* __restrict__ x,
                 const float* __restrict__ ma,
                 const float* __restrict__ mv,
                 const float* __restrict__ Wq,
                 const float* __restrict__ Wv,
                 const float* __restrict__ Wg,
                 const float* __restrict__ bg,
                 float* __restrict__ out)
{
    extern __shared__ float sm[];
    __shared__ int flag_s;
    const uint32_t sb = smem_u32(sm);
    const int tid  = threadIdx.x;
    const int bx   = blockIdx.x;   // 0..3
    const int b    = blockIdx.y;   // 0..63
    const int lane = tid & 31;
    const int warp = tid >> 5;
    const int g    = lane >> 2;
    const int tc   = lane & 3;
    const int m0   = warp * 16;

    // ---- constants ----
    for (int i = tid; i < 48 * 64; i += 256) {
        int r = i >> 6, d = i & 63;
        float v = (r < 32) ? Wq[i] : ((r == 32) ? Wg[d] : 0.0f);
        sm[O_WQS + r * PW + d] = tf32r(v);
    }
    if (tid < SLOTS) {
        float a[ADIM]; float ss = 0.0f;
        #pragma unroll
        for (int k = 0; k < ADIM; k++) { a[k] = ma[tid * ADIM + k]; ss += a[k] * a[k]; }
        float r4 = 4.0f / fmaxf(sqrtf(ss), 1e-12f);
        #pragma unroll
        for (int k = 0; k < ADIM; k++)
            sm[O_AS + tid * PQ + k] = tf32r(a[k] * r4);
    }
    const float bgv = bg[0];

    // ---- per-lane ldmatrix bases ----
    const int l7  = lane & 7;
    const int lml = (lane >> 3) & 1;
    const int lmh = lane >> 4;
    const int lhi = lane >> 4;
    const int lcm = (lane >> 3) & 1;

    const int s0  = (warp & 3) * 16;
    const int ntb = (warp >> 2) * 4;

    const uint32_t aWW = sb + (uint32_t)(O_WWS + (s0 + l7 + 8 * lml) * PT + 4 * lmh) * 4;
    const uint32_t aQS = sb + (uint32_t)(O_QS  + (m0 + l7 + 8 * lml) * PQ + 4 * lmh) * 4;
    const uint32_t bAS = sb + (uint32_t)(O_AS  + (lhi * 8 + l7) * PQ + 4 * lcm) * 4;
    const uint32_t bWQ = sb + (uint32_t)(O_WQS + (lhi * 8 + l7) * PW + 4 * lcm) * 4;
    const int rowX0 = (ntb + 0 + lhi) * 8 + l7;
    const int rowX2 = (ntb + 2 + lhi) * 8 + l7;
    const uint32_t bX0 = sb + (uint32_t)(O_XTS + rowX0 * PT) * 4;
    const uint32_t bX2 = sb + (uint32_t)(O_XTS + rowX2 * PT) * 4;
    const uint32_t keyX0 = (rowX0 >> 2) & 7, keyX2 = (rowX2 >> 2) & 7;

    float cp[4][4];
    #pragma unroll
    for (int j = 0; j < 4; j++)
        #pragma unroll
        for (int u = 0; u < 4; u++) cp[j][u] = 0.0f;
    float wsum = 0.0f;

    const int tA = m0 + g, tB = m0 + g + 8;
    const int cA = tA >> 2, wA = tA & 3, cB = tB >> 2, wB = tB & 3;

    // ---- prefetch chunk 0 into registers ----
    float4 xr[8];
    {
        const float4* xg = (const float4*)(x + ((size_t)b * TOKENS + (bx * NCHUNK) * TILE_T) * EDIM);
        #pragma unroll
        for (int k = 0; k < 8; k++) xr[k] = __ldg(&xg[tid + k * 256]);
    }
    __syncthreads();   // constants ready

    for (int c = 0; c < NCHUNK; c++) {
        // ---- store prefetched x -> swizzled x^T (tf32) ----
        #pragma unroll
        for (int k = 0; k < 8; k++) {
            int f = tid + k * 256;
            int t = f >> 4, d = (f & 15) * 4;
            sm[xidx(d + 0, t)] = tf32r(xr[k].x);
            sm[xidx(d + 1, t)] = tf32r(xr[k].y);
            sm[xidx(d + 2, t)] = tf32r(xr[k].z);
            sm[xidx(d + 3, t)] = tf32r(xr[k].w);
        }
        __syncthreads();   // (A) XTS ready

        // ============ Q-GEMM: C_q[16t x 40] = x @ [Wq;Wg]^T ============
        float cq[5][4];
        #pragma unroll
        for (int nt = 0; nt < 5; nt++)
            #pragma unroll
            for (int u = 0; u < 4; u++) cq[nt][u] = 0.0f;
        #pragma unroll
        for (int k = 0; k < 8; k++) {
            const int k8 = k * 8;
            const int d0 = k8 + tc, d1 = k8 + tc + 4;
            const int k0 = (k8 >> 2) & 7, k1 = ((k8 >> 2) + 1) & 7;
            uint32_t a0 = U(sm[O_XTS + d0 * PT + (((cA ^ k0) << 2) | wA)]);
            uint32_t a1 = U(sm[O_XTS + d0 * PT + (((cB ^ k0) << 2) | wB)]);
            uint32_t a2 = U(sm[O_XTS + d1 * PT + (((cA ^ k1) << 2) | wA)]);
            uint32_t a3 = U(sm[O_XTS + d1 * PT + (((cB ^ k1) << 2) | wB)]);
            uint32_t bq0[4], bq1[4], bq2[4];
            ldm4(bq0, bWQ + (uint32_t)(k8 * 4));
            ldm4(bq1, bWQ + (uint32_t)(2 * 8 * PW * 4 + k8 * 4));
            ldm4(bq2, bWQ + (uint32_t)(4 * 8 * PW * 4 + k8 * 4));
            mma8(cq[0], a0, a1, a2, a3, bq0[0], bq0[1]);
            mma8(cq[1], a0, a1, a2, a3, bq0[2], bq0[3]);
            mma8(cq[2], a0, a1, a2, a3, bq1[0], bq1[1]);
            mma8(cq[3], a0, a1, a2, a3, bq1[2], bq1[3]);
            mma8(cq[4], a0, a1, a2, a3, bq2[0], bq2[1]);
        }
        float ss0 = 0.f, ss1 = 0.f;
        #pragma unroll
        for (int nt = 0; nt < 4; nt++) {
            ss0 += cq[nt][0] * cq[nt][0] + cq[nt][1] * cq[nt][1];
            ss1 += cq[nt][2] * cq[nt][2] + cq[nt][3] * cq[nt][3];
        }
        ss0 += __shfl_xor_sync(0xffffffffu, ss0, 1);
        ss0 += __shfl_xor_sync(0xffffffffu, ss0, 2);
        ss1 += __shfl_xor_sync(0xffffffffu, ss1, 1);
        ss1 += __shfl_xor_sync(0xffffffffu, ss1, 2);
        const float rs0 = 1.0f / fmaxf(sqrtf(ss0), 1e-12f);
        const float rs1 = 1.0f / fmaxf(sqrtf(ss1), 1e-12f);
        const float gl0 = __shfl_sync(0xffffffffu, cq[4][0], lane & ~3);
        const float gl1 = __shfl_sync(0xffffffffu, cq[4][2], lane & ~3);
        const float gate0 = 1.0f / (1.0f + __expf(-(gl0 + bgv)));
        const float gate1 = 1.0f / (1.0f + __expf(-(gl1 + bgv)));
        #pragma unroll
        for (int nt = 0; nt < 4; nt++) {
            const int col = nt * 8 + 2 * tc;
            sm[O_QS + tA * PQ + col]     = tf32r(cq[nt][0] * rs0);
            sm[O_QS + tA * PQ + col + 1] = tf32r(cq[nt][1] * rs0);
            sm[O_QS + tB * PQ + col]     = tf32r(cq[nt][2] * rs1);
            sm[O_QS + tB * PQ + col + 1] = tf32r(cq[nt][3] * rs1);
        }
        __syncwarp();

        // ============ S-GEMM: C_s[16t x 64s] = qhat @ (4*ahat)^T ============
        float cs[8][4];
        #pragma unroll
        for (int nt = 0; nt < 8; nt++)
            #pragma unroll
            for (int u = 0; u < 4; u++) cs[nt][u] = 0.0f;
        #pragma unroll
        for (int k = 0; k < 4; k++) {
            const int k8 = k * 8;
            uint32_t aq[4];
            ldm4(aq, aQS + (uint32_t)(k8 * 4));
            #pragma unroll
            for (int jp = 0; jp < 4; jp++) {
                uint32_t bs[4];
                ldm4(bs, bAS + (uint32_t)(jp * 2 * 8 * PQ * 4 + k8 * 4));
                mma8(cs[jp * 2],     aq[0], aq[1], aq[2], aq[3], bs[0], bs[1]);
                mma8(cs[jp * 2 + 1], aq[0], aq[1], aq[2], aq[3], bs[2], bs[3]);
            }
        }
        float z0 = 0.f, z1 = 0.f;
        #pragma unroll
        for (int nt = 0; nt < 8; nt++) {
            cs[nt][0] = __expf(cs[nt][0]); z0 += cs[nt][0];
            cs[nt][1] = __expf(cs[nt][1]); z0 += cs[nt][1];
            cs[nt][2] = __expf(cs[nt][2]); z1 += cs[nt][2];
            cs[nt][3] = __expf(cs[nt][3]); z1 += cs[nt][3];
        }
        z0 += __shfl_xor_sync(0xffffffffu, z0, 1);
        z0 += __shfl_xor_sync(0xffffffffu, z0, 2);
        z1 += __shfl_xor_sync(0xffffffffu, z1, 1);
        z1 += __shfl_xor_sync(0xffffffffu, z1, 2);
        const float k0 = gate0 / z0, k1 = gate1 / z1;
        #pragma unroll
        for (int nt = 0; nt < 8; nt++) {
            const int s = nt * 8 + 2 * tc;
            sm[O_WWS + s       * PT + tA] = tf32r(cs[nt][0] * k0);
            sm[O_WWS + (s + 1) * PT + tA] = tf32r(cs[nt][1] * k0);
            sm[O_WWS + s       * PT + tB] = tf32r(cs[nt][2] * k1);
            sm[O_WWS + (s + 1) * PT + tB] = tf32r(cs[nt][3] * k1);
        }
        __syncthreads();   // (B) WWS ready

        // ---- prefetch next chunk (overlaps P-GEMM) ----
        if (c + 1 < NCHUNK) {
            const float4* xg = (const float4*)(x + ((size_t)b * TOKENS + (bx * NCHUNK + c + 1) * TILE_T) * EDIM);
            #pragma unroll
            for (int k = 0; k < 8; k++) xr[k] = __ldg(&xg[tid + k * 256]);
        }

        // ---- W partial sums (threads 0..63) ----
        if (tid < SLOTS) {
            const float2* wr = (const float2*)&sm[O_WWS + tid * PT];
            float s = 0.f;
            #pragma unroll 16
            for (int t2 = 0; t2 < TILE_T / 2; t2++) { float2 v = wr[t2]; s += v.x + v.y; }
            wsum += s;
        }

        // ============ P-GEMM: cp[16s x 32e] += ww^T @ x ============
        #pragma unroll
        for (int k = 0; k < 16; k++) {
            const int k8 = k * 8;
            uint32_t ap[4], b0[4], b1[4];
            ldm4(ap, aWW + (uint32_t)(k8 * 4));
            const uint32_t ch = (uint32_t)((k8 >> 2) + lcm);
            ldm4(b0, bX0 + ((ch ^ keyX0) << 4));
            ldm4(b1, bX2 + ((ch ^ keyX2) << 4));
            mma8(cp[0], ap[0], ap[1], ap[2], ap[3], b0[0], b0[1]);
            mma8(cp[1], ap[0], ap[1], ap[2], ap[3], b0[2], b0[3]);
            mma8(cp[2], ap[0], ap[1], ap[2], ap[3], b1[0], b1[1]);
            mma8(cp[3], ap[0], ap[1], ap[2], ap[3], b1[2], b1[3]);
        }
        __syncthreads();   // (C) XTS/WWS consumers done before next overwrite
    }

    // ---- flush partials (exclusive slices) ----
    float* dst = &g_Ppart[((size_t)(bx * BATCH + b)) * SLOTS * EDIM];
    #pragma unroll
    for (int j = 0; j < 4; j++) {
        const int e = (ntb + j) * 8 + 2 * tc;
        dst[(s0 + g)     * EDIM + e]     = cp[j][0];
        dst[(s0 + g)     * EDIM + e + 1] = cp[j][1];
        dst[(s0 + g + 8) * EDIM + e]     = cp[j][2];
        dst[(s0 + g + 8) * EDIM + e + 1] = cp[j][3];
    }
    if (tid < SLOTS) g_Wpart[(bx * BATCH + b) * SLOTS + tid] = wsum;

    // ---- last CTA per batch finalizes ----
    __threadfence();
    if (tid == 0) flag_s = atomicAdd(&g_cnt[b], 1);
    __syncthreads();
    if (flag_s != BPB - 1) return;
    if (tid == 0) g_cnt[b] = 0;          // reset for next graph replay
    __threadfence();                      // acquire partials

    for (int i = tid; i < SLOTS * EDIM; i += 256) {
        const int s = i >> 6, d = i & 63;
        float p = 0.f;
        #pragma unroll
        for (int k = 0; k < BPB; k++)
            p += g_Ppart[((size_t)(k * BATCH + b)) * SLOTS * EDIM + i];
        sm[F_PT + d * 68 + s] = p;        // Pt[d][s]
        sm[F_WV + d * 68 + s] = Wv[i];    // WvT[d][e]
    }
    if (tid < SLOTS) {
        float w = 0.f;
        #pragma unroll
        for (int k = 0; k < BPB; k++)
            w += g_Wpart[(k * BATCH + b) * SLOTS + tid];
        sm[F_WS + tid] = w;
    }
    __syncthreads();

    const int s  = tid >> 2;              // 0..63
    const int eb = (tid & 3) * 16;        // 0,16,32,48
    float acc[16];
    #pragma unroll
    for (int j = 0; j < 16; j++) acc[j] = 0.f;
    #pragma unroll 8
    for (int d = 0; d < EDIM; d++) {
        const float pv = sm[F_PT + d * 68 + s];
        #pragma unroll
        for (int j4 = 0; j4 < 4; j4++) {
            const float4 w4 = *(const float4*)&sm[F_WV + d * 68 + eb + j4 * 4];
            acc[j4 * 4 + 0] += pv * w4.x;
            acc[j4 * 4 + 1] += pv * w4.y;
            acc[j4 * 4 + 2] += pv * w4.z;
            acc[j4 * 4 + 3] += pv * w4.w;
        }
    }
    const float W  = sm[F_WS + s];
    const float em = __expf(-W);                      // 1-g
    const float sc = (1.0f - em) / fmaxf(W, 1e-6f);   // g/max(W,1e-6)
    const float* mvr = mv + ((size_t)b * SLOTS + s) * EDIM + eb;
    float* outr = out + ((size_t)b * SLOTS + s) * EDIM + eb;
    #pragma unroll
    for (int j = 0; j < 16; j += 4) {
        float4 m4 = *(const float4*)(mvr + j);
        float4 o;
        o.x = m4.x * em + acc[j]     * sc;
        o.y = m4.y * em + acc[j + 1] * sc;
        o.z = m4.z * em + acc[j + 2] * sc;
        o.w = m4.w * em + acc[j + 3] * sc;
        *(float4*)(outr + j) = o;
    }
}

// ============================================================
extern "C" void kernel_launch(void* const* d_in, const int* in_sizes, int n_in,
                              void* d_out, int out_size) {
    const float* x  = (const float*)d_in[0];
    const float* ma = (const float*)d_in[1];
    const float* mv = (const float*)d_in[2];
    const float* Wq = (const float*)d_in[3];
    const float* Wv = (const float*)d_in[4];
    const float* Wg = (const float*)d_in[5];
    const float* bg = (const float*)d_in[6];
    float* out = (float*)d_out;
    (void)in_sizes; (void)n_in; (void)out_size;

    cudaFuncSetAttribute(main_kernel,
                         cudaFuncAttributeMaxDynamicSharedMemorySize, SM_BYTES);

    dim3 grid(BPB, BATCH);
    main_kernel<<<grid, 256, SM_BYTES>>>(x, ma, mv, Wq, Wv, Wg, bg, out);
}

// round 11
// speedup vs baseline: 1.0417x; 1.0417x over previous
#include <cuda_runtime.h>
#include <math.h>
#include <stdint.h>

#define BATCH  64
#define TOKENS 4096
#define SLOTS  64
#define ADIM   32
#define EDIM   64
#define TILE_T 128
#define NCHUNK 8
#define BPB    4      // blocks per batch; BPB*NCHUNK*TILE_T == TOKENS

// padded strides (floats): all ≡ 4 (mod 32) and 16B-multiples -> ldmatrix conflict-free
#define PT 132
#define PQ 36
#define PW 68

// shared float offsets (main phase)
#define O_XTS 0                      // [64 d][PT]  x^T tf32 (XOR-swizzled chunks)
#define O_WWS (O_XTS + 64 * PT)      // [64 s][PT]  ww^T tf32 (linear)
#define O_QS  (O_WWS + 64 * PT)      // [128 t][PQ] qhat tf32
#define O_WQS (O_QS  + 128 * PQ)     // [48 a][PW]  Wq 0-31, Wg 32, 33-47 zero
#define O_AS  (O_WQS + 48 * PW)      // [64 s][PQ]  4*ahat tf32
#define SM_FLOATS (O_AS + 64 * PQ)
#define SM_BYTES  (SM_FLOATS * 4)    // 108288 B -> 2 CTAs/SM

// finalize-phase smem reuse (stride 68 => float4-aligned rows)
#define F_PT  0                      // Pt[d][s]  64 x 68
#define F_WV  (F_PT + 64 * 68)       // WvT[d][e] 64 x 68
#define F_WS  (F_WV + 64 * 68)       // [64] W sums

__device__ float g_Ppart[BPB * BATCH * SLOTS * EDIM];   // [bx][b][s][e]
__device__ float g_Wpart[BPB * BATCH * SLOTS];
__device__ int   g_cnt[BATCH];                          // zero-init; self-resetting

__device__ __forceinline__ float tf32r(float f) {
    uint32_t u; asm("cvt.rna.tf32.f32 %0, %1;" : "=r"(u) : "f"(f));
    return __uint_as_float(u);
}
__device__ __forceinline__ void mma8(float* c, uint32_t a0, uint32_t a1,
                                     uint32_t a2, uint32_t a3,
                                     uint32_t b0, uint32_t b1) {
    asm volatile("mma.sync.aligned.m16n8k8.row.col.f32.tf32.tf32.f32 "
        "{%0,%1,%2,%3}, {%4,%5,%6,%7}, {%8,%9}, {%0,%1,%2,%3};"
        : "+f"(c[0]), "+f"(c[1]), "+f"(c[2]), "+f"(c[3])
        : "r"(a0), "r"(a1), "r"(a2), "r"(a3), "r"(b0), "r"(b1));
}
__device__ __forceinline__ void ldm4(uint32_t* r, uint32_t a) {
    asm volatile("ldmatrix.sync.aligned.m8n8.x4.shared.b16 {%0,%1,%2,%3}, [%4];"
        : "=r"(r[0]), "=r"(r[1]), "=r"(r[2]), "=r"(r[3]) : "r"(a));
}
__device__ __forceinline__ uint32_t smem_u32(const void* p) {
    uint32_t a;
    asm("{ .reg .u64 t; cvta.to.shared.u64 t, %1; cvt.u32.u64 %0, t; }" : "=r"(a) : "l"(p));
    return a;
}
// XTS swizzled float index: row d, element t
__device__ __forceinline__ int xidx(int d, int t) {
    return O_XTS + d * PT + ((((t >> 2) ^ ((d >> 2) & 7)) << 2) | (t & 3));
}
#define U(x) __float_as_uint(x)

// ============================================================
// single fused kernel: grid (BPB, BATCH), 256 threads
// ============================================================
__global__ __launch_bounds__(256, 2)
void main_kernel(const float* __restrict__ x,
                 const float* __restrict__ ma,
                 const float* __restrict__ mv,
                 const float* __restrict__ Wq,
                 const float* __restrict__ Wv,
                 const float* __restrict__ Wg,
                 const float* __restrict__ bg,
                 float* __restrict__ out)
{
    extern __shared__ float sm[];
    __shared__ int flag_s;
    const uint32_t sb = smem_u32(sm);
    const int tid  = threadIdx.x;
    const int bx   = blockIdx.x;   // 0..3
    const int b    = blockIdx.y;   // 0..63
    const int lane = tid & 31;
    const int warp = tid >> 5;
    const int g    = lane >> 2;
    const int tc   = lane & 3;
    const int m0   = warp * 16;

    // ---- constants ----
    for (int i = tid; i < 48 * 64; i += 256) {
        int r = i >> 6, d = i & 63;
        float v = (r < 32) ? Wq[i] : ((r == 32) ? Wg[d] : 0.0f);
        sm[O_WQS + r * PW + d] = tf32r(v);
    }
    if (tid < SLOTS) {
        float a[ADIM]; float ss = 0.0f;
        #pragma unroll
        for (int k = 0; k < ADIM; k++) { a[k] = ma[tid * ADIM + k]; ss += a[k] * a[k]; }
        float r4 = 4.0f / fmaxf(sqrtf(ss), 1e-12f);
        #pragma unroll
        for (int k = 0; k < ADIM; k++)
            sm[O_AS + tid * PQ + k] = tf32r(a[k] * r4);
    }
    const float bgv = bg[0];

    // ---- per-lane ldmatrix bases ----
    const int l7  = lane & 7;
    const int lml = (lane >> 3) & 1;
    const int lmh = lane >> 4;
    const int lhi = lane >> 4;
    const int lcm = (lane >> 3) & 1;

    const int s0  = (warp & 3) * 16;
    const int ntb = (warp >> 2) * 4;

    const uint32_t aWW = sb + (uint32_t)(O_WWS + (s0 + l7 + 8 * lml) * PT + 4 * lmh) * 4;
    const uint32_t aQS = sb + (uint32_t)(O_QS  + (m0 + l7 + 8 * lml) * PQ + 4 * lmh) * 4;
    const uint32_t bAS = sb + (uint32_t)(O_AS  + (lhi * 8 + l7) * PQ + 4 * lcm) * 4;
    const uint32_t bWQ = sb + (uint32_t)(O_WQS + (lhi * 8 + l7) * PW + 4 * lcm) * 4;
    const int rowX0 = (ntb + 0 + lhi) * 8 + l7;
    const int rowX2 = (ntb + 2 + lhi) * 8 + l7;
    const uint32_t bX0 = sb + (uint32_t)(O_XTS + rowX0 * PT) * 4;
    const uint32_t bX2 = sb + (uint32_t)(O_XTS + rowX2 * PT) * 4;
    const uint32_t keyX0 = (rowX0 >> 2) & 7, keyX2 = (rowX2 >> 2) & 7;

    float cp[4][4];
    #pragma unroll
    for (int j = 0; j < 4; j++)
        #pragma unroll
        for (int u = 0; u < 4; u++) cp[j][u] = 0.0f;
    float wsum = 0.0f;

    const int tA = m0 + g, tB = m0 + g + 8;
    const int cA = tA >> 2, wA = tA & 3, cB = tB >> 2, wB = tB & 3;

    __syncthreads();   // constants ready

    for (int c = 0; c < NCHUNK; c++) {
        // ---- load x chunk -> swizzled x^T (tf32); no register prefetch (reg pressure) ----
        const float4* xg = (const float4*)(x + ((size_t)b * TOKENS + (bx * NCHUNK + c) * TILE_T) * EDIM);
        #pragma unroll
        for (int k = 0; k < 8; k++) {
            int f = tid + k * 256;
            float4 v = __ldg(&xg[f]);
            int t = f >> 4, d = (f & 15) * 4;
            sm[xidx(d + 0, t)] = tf32r(v.x);
            sm[xidx(d + 1, t)] = tf32r(v.y);
            sm[xidx(d + 2, t)] = tf32r(v.z);
            sm[xidx(d + 3, t)] = tf32r(v.w);
        }
        __syncthreads();   // (A) XTS ready

        // ============ Q-GEMM: C_q[16t x 40] = x @ [Wq;Wg]^T ============
        float cq[5][4];
        #pragma unroll
        for (int nt = 0; nt < 5; nt++)
            #pragma unroll
            for (int u = 0; u < 4; u++) cq[nt][u] = 0.0f;
        #pragma unroll
        for (int k = 0; k < 8; k++) {
            const int k8 = k * 8;
            const int d0 = k8 + tc, d1 = k8 + tc + 4;
            const int k0 = (k8 >> 2) & 7, k1 = ((k8 >> 2) + 1) & 7;
            uint32_t a0 = U(sm[O_XTS + d0 * PT + (((cA ^ k0) << 2) | wA)]);
            uint32_t a1 = U(sm[O_XTS + d0 * PT + (((cB ^ k0) << 2) | wB)]);
            uint32_t a2 = U(sm[O_XTS + d1 * PT + (((cA ^ k1) << 2) | wA)]);
            uint32_t a3 = U(sm[O_XTS + d1 * PT + (((cB ^ k1) << 2) | wB)]);
            uint32_t bq0[4], bq1[4], bq2[4];
            ldm4(bq0, bWQ + (uint32_t)(k8 * 4));
            ldm4(bq1, bWQ + (uint32_t)(2 * 8 * PW * 4 + k8 * 4));
            ldm4(bq2, bWQ + (uint32_t)(4 * 8 * PW * 4 + k8 * 4));
            mma8(cq[0], a0, a1, a2, a3, bq0[0], bq0[1]);
            mma8(cq[1], a0, a1, a2, a3, bq0[2], bq0[3]);
            mma8(cq[2], a0, a1, a2, a3, bq1[0], bq1[1]);
            mma8(cq[3], a0, a1, a2, a3, bq1[2], bq1[3]);
            mma8(cq[4], a0, a1, a2, a3, bq2[0], bq2[1]);
        }
        float ss0 = 0.f, ss1 = 0.f;
        #pragma unroll
        for (int nt = 0; nt < 4; nt++) {
            ss0 += cq[nt][0] * cq[nt][0] + cq[nt][1] * cq[nt][1];
            ss1 += cq[nt][2] * cq[nt][2] + cq[nt][3] * cq[nt][3];
        }
        ss0 += __shfl_xor_sync(0xffffffffu, ss0, 1);
        ss0 += __shfl_xor_sync(0xffffffffu, ss0, 2);
        ss1 += __shfl_xor_sync(0xffffffffu, ss1, 1);
        ss1 += __shfl_xor_sync(0xffffffffu, ss1, 2);
        const float rs0 = 1.0f / fmaxf(sqrtf(ss0), 1e-12f);
        const float rs1 = 1.0f / fmaxf(sqrtf(ss1), 1e-12f);
        const float gl0 = __shfl_sync(0xffffffffu, cq[4][0], lane & ~3);
        const float gl1 = __shfl_sync(0xffffffffu, cq[4][2], lane & ~3);
        const float gate0 = 1.0f / (1.0f + __expf(-(gl0 + bgv)));
        const float gate1 = 1.0f / (1.0f + __expf(-(gl1 + bgv)));
        #pragma unroll
        for (int nt = 0; nt < 4; nt++) {
            const int col = nt * 8 + 2 * tc;
            sm[O_QS + tA * PQ + col]     = tf32r(cq[nt][0] * rs0);
            sm[O_QS + tA * PQ + col + 1] = tf32r(cq[nt][1] * rs0);
            sm[O_QS + tB * PQ + col]     = tf32r(cq[nt][2] * rs1);
            sm[O_QS + tB * PQ + col + 1] = tf32r(cq[nt][3] * rs1);
        }
        __syncwarp();

        // ============ S-GEMM: C_s[16t x 64s] = qhat @ (4*ahat)^T ============
        float cs[8][4];
        #pragma unroll
        for (int nt = 0; nt < 8; nt++)
            #pragma unroll
            for (int u = 0; u < 4; u++) cs[nt][u] = 0.0f;
        #pragma unroll
        for (int k = 0; k < 4; k++) {
            const int k8 = k * 8;
            uint32_t aq[4];
            ldm4(aq, aQS + (uint32_t)(k8 * 4));
            #pragma unroll
            for (int jp = 0; jp < 4; jp++) {
                uint32_t bs[4];
                ldm4(bs, bAS + (uint32_t)(jp * 2 * 8 * PQ * 4 + k8 * 4));
                mma8(cs[jp * 2],     aq[0], aq[1], aq[2], aq[3], bs[0], bs[1]);
                mma8(cs[jp * 2 + 1], aq[0], aq[1], aq[2], aq[3], bs[2], bs[3]);
            }
        }
        float z0 = 0.f, z1 = 0.f;
        #pragma unroll
        for (int nt = 0; nt < 8; nt++) {
            cs[nt][0] = __expf(cs[nt][0]); z0 += cs[nt][0];
            cs[nt][1] = __expf(cs[nt][1]); z0 += cs[nt][1];
            cs[nt][2] = __expf(cs[nt][2]); z1 += cs[nt][2];
            cs[nt][3] = __expf(cs[nt][3]); z1 += cs[nt][3];
        }
        z0 += __shfl_xor_sync(0xffffffffu, z0, 1);
        z0 += __shfl_xor_sync(0xffffffffu, z0, 2);
        z1 += __shfl_xor_sync(0xffffffffu, z1, 1);
        z1 += __shfl_xor_sync(0xffffffffu, z1, 2);
        const float k0 = gate0 / z0, k1 = gate1 / z1;
        #pragma unroll
        for (int nt = 0; nt < 8; nt++) {
            const int s = nt * 8 + 2 * tc;
            sm[O_WWS + s       * PT + tA] = tf32r(cs[nt][0] * k0);
            sm[O_WWS + (s + 1) * PT + tA] = tf32r(cs[nt][1] * k0);
            sm[O_WWS + s       * PT + tB] = tf32r(cs[nt][2] * k1);
            sm[O_WWS + (s + 1) * PT + tB] = tf32r(cs[nt][3] * k1);
        }
        __syncthreads();   // (B) WWS ready

        // ---- W partial sums (threads 0..63) ----
        if (tid < SLOTS) {
            const float2* wr = (const float2*)&sm[O_WWS + tid * PT];
            float s = 0.f;
            #pragma unroll 16
            for (int t2 = 0; t2 < TILE_T / 2; t2++) { float2 v = wr[t2]; s += v.x + v.y; }
            wsum += s;
        }

        // ============ P-GEMM: cp[16s x 32e] += ww^T @ x ============
        #pragma unroll
        for (int k = 0; k < 16; k++) {
            const int k8 = k * 8;
            uint32_t ap[4], b0[4], b1[4];
            ldm4(ap, aWW + (uint32_t)(k8 * 4));
            const uint32_t ch = (uint32_t)((k8 >> 2) + lcm);
            ldm4(b0, bX0 + ((ch ^ keyX0) << 4));
            ldm4(b1, bX2 + ((ch ^ keyX2) << 4));
            mma8(cp[0], ap[0], ap[1], ap[2], ap[3], b0[0], b0[1]);
            mma8(cp[1], ap[0], ap[1], ap[2], ap[3], b0[2], b0[3]);
            mma8(cp[2], ap[0], ap[1], ap[2], ap[3], b1[0], b1[1]);
            mma8(cp[3], ap[0], ap[1], ap[2], ap[3], b1[2], b1[3]);
        }
        __syncthreads();   // (C) XTS/WWS consumers done before next overwrite
    }

    // ---- flush partials (exclusive slices) ----
    float* dst = &g_Ppart[((size_t)(bx * BATCH + b)) * SLOTS * EDIM];
    #pragma unroll
    for (int j = 0; j < 4; j++) {
        const int e = (ntb + j) * 8 + 2 * tc;
        dst[(s0 + g)     * EDIM + e]     = cp[j][0];
        dst[(s0 + g)     * EDIM + e + 1] = cp[j][1];
        dst[(s0 + g + 8) * EDIM + e]     = cp[j][2];
        dst[(s0 + g + 8) * EDIM + e + 1] = cp[j][3];
    }
    if (tid < SLOTS) g_Wpart[(bx * BATCH + b) * SLOTS + tid] = wsum;

    // ---- last CTA per batch finalizes ----
    __threadfence();
    if (tid == 0) flag_s = atomicAdd(&g_cnt[b], 1);
    __syncthreads();
    if (flag_s != BPB - 1) return;
    if (tid == 0) g_cnt[b] = 0;          // reset for next graph replay
    __threadfence();                      // acquire partials

    for (int i = tid; i < SLOTS * EDIM; i += 256) {
        const int s = i >> 6, d = i & 63;
        float p = 0.f;
        #pragma unroll
        for (int k = 0; k < BPB; k++)
            p += g_Ppart[((size_t)(k * BATCH + b)) * SLOTS * EDIM + i];
        sm[F_PT + d * 68 + s] = p;        // Pt[d][s]
        sm[F_WV + d * 68 + s] = Wv[i];    // WvT[d][e]
    }
    if (tid < SLOTS) {
        float w = 0.f;
        #pragma unroll
        for (int k = 0; k < BPB; k++)
            w += g_Wpart[(k * BATCH + b) * SLOTS + tid];
        sm[F_WS + tid] = w;
    }
    __syncthreads();

    const int s  = tid >> 2;              // 0..63
    const int eb = (tid & 3) * 16;        // 0,16,32,48
    float acc[16];
    #pragma unroll
    for (int j = 0; j < 16; j++) acc[j] = 0.f;
    #pragma unroll 8
    for (int d = 0; d < EDIM; d++) {
        const float pv = sm[F_PT + d * 68 + s];
        #pragma unroll
        for (int j4 = 0; j4 < 4; j4++) {
            const float4 w4 = *(const float4*)&sm[F_WV + d * 68 + eb + j4 * 4];
            acc[j4 * 4 + 0] += pv * w4.x;
            acc[j4 * 4 + 1] += pv * w4.y;
            acc[j4 * 4 + 2] += pv * w4.z;
            acc[j4 * 4 + 3] += pv * w4.w;
        }
    }
    const float W  = sm[F_WS + s];
    const float em = __expf(-W);                      // 1-g
    const float sc = (1.0f - em) / fmaxf(W, 1e-6f);   // g/max(W,1e-6)
    const float* mvr = mv + ((size_t)b * SLOTS + s) * EDIM + eb;
    float* outr = out + ((size_t)b * SLOTS + s) * EDIM + eb;
    #pragma unroll
    for (int j = 0; j < 16; j += 4) {
        float4 m4 = *(const float4*)(mvr + j);
        float4 o;
        o.x = m4.x * em + acc[j]     * sc;
        o.y = m4.y * em + acc[j + 1] * sc;
        o.z = m4.z * em + acc[j + 2] * sc;
        o.w = m4.w * em + acc[j + 3] * sc;
        *(float4*)(outr + j) = o;
    }
}

// ============================================================
extern "C" void kernel_launch(void* const* d_in, const int* in_sizes, int n_in,
                              void* d_out, int out_size) {
    const float* x  = (const float*)d_in[0];
    const float* ma = (const float*)d_in[1];
    const float* mv = (const float*)d_in[2];
    const float* Wq = (const float*)d_in[3];
    const float* Wv = (const float*)d_in[4];
    const float* Wg = (const float*)d_in[5];
    const float* bg = (const float*)d_in[6];
    float* out = (float*)d_out;
    (void)in_sizes; (void)n_in; (void)out_size;

    cudaFuncSetAttribute(main_kernel,
                         cudaFuncAttributeMaxDynamicSharedMemorySize, SM_BYTES);

    dim3 grid(BPB, BATCH);
    main_kernel<<<grid, 256, SM_BYTES>>>(x, ma, mv, Wq, Wv, Wg, bg, out);
}

// round 12
// speedup vs baseline: 1.2758x; 1.2248x over previous
#include <cuda_runtime.h>
#include <math.h>
#include <stdint.h>

#define BATCH  64
#define TOKENS 4096
#define SLOTS  64
#define ADIM   32
#define EDIM   64
#define TILE_T 128
#define NCHUNK 8
#define BPB    4      // blocks per batch; BPB*NCHUNK*TILE_T == TOKENS

// padded strides (floats): all ≡ 4 (mod 32) and 16B-multiples -> ldmatrix conflict-free
#define PT 132
#define PQ 36
#define PW 68

// shared float offsets (main phase)
#define O_XTS 0                      // [64 d][PT]  x^T tf32 (XOR-swizzled chunks)
#define O_WWS (O_XTS + 64 * PT)      // [64 s][PT]  ww^T tf32 (linear)
#define O_QS  (O_WWS + 64 * PT)      // [128 t][PQ] qhat tf32
#define O_WQS (O_QS  + 128 * PQ)     // [48 a][PW]  Wq 0-31, Wg 32, 33-47 zero
#define O_AS  (O_WQS + 48 * PW)      // [64 s][PQ]  4*ahat tf32
#define SM_FLOATS (O_AS + 64 * PQ)
#define SM_BYTES  (SM_FLOATS * 4)    // 108288 B -> 2 CTAs/SM

__device__ float g_Ppart[BPB * BATCH * SLOTS * EDIM];   // [bx][b][s][e]
__device__ float g_Wpart[BPB * BATCH * SLOTS];

__device__ __forceinline__ float tf32r(float f) {
    uint32_t u; asm("cvt.rna.tf32.f32 %0, %1;" : "=r"(u) : "f"(f));
    return __uint_as_float(u);
}
__device__ __forceinline__ void mma8(float* c, uint32_t a0, uint32_t a1,
                                     uint32_t a2, uint32_t a3,
                                     uint32_t b0, uint32_t b1) {
    asm volatile("mma.sync.aligned.m16n8k8.row.col.f32.tf32.tf32.f32 "
        "{%0,%1,%2,%3}, {%4,%5,%6,%7}, {%8,%9}, {%0,%1,%2,%3};"
        : "+f"(c[0]), "+f"(c[1]), "+f"(c[2]), "+f"(c[3])
        : "r"(a0), "r"(a1), "r"(a2), "r"(a3), "r"(b0), "r"(b1));
}
__device__ __forceinline__ void ldm4(uint32_t* r, uint32_t a) {
    asm volatile("ldmatrix.sync.aligned.m8n8.x4.shared.b16 {%0,%1,%2,%3}, [%4];"
        : "=r"(r[0]), "=r"(r[1]), "=r"(r[2]), "=r"(r[3]) : "r"(a));
}
__device__ __forceinline__ uint32_t smem_u32(const void* p) {
    uint32_t a;
    asm("{ .reg .u64 t; cvta.to.shared.u64 t, %1; cvt.u32.u64 %0, t; }" : "=r"(a) : "l"(p));
    return a;
}
// XTS swizzled float index: row d, element t
__device__ __forceinline__ int xidx(int d, int t) {
    return O_XTS + d * PT + ((((t >> 2) ^ ((d >> 2) & 7)) << 2) | (t & 3));
}
#define U(x) __float_as_uint(x)

// ============================================================
// main: block handles 1024 tokens of one batch (8 chunks of 128)
// ============================================================
__global__ __launch_bounds__(256, 2)
void main_kernel(const float* __restrict__ x,
                 const float* __restrict__ ma,
                 const float* __restrict__ Wq,
                 const float* __restrict__ Wg,
                 const float* __restrict__ bg)
{
    extern __shared__ float sm[];
    const uint32_t sb = smem_u32(sm);
    const int tid  = threadIdx.x;
    const int bx   = blockIdx.x;   // 0..3
    const int b    = blockIdx.y;   // 0..63
    const int lane = tid & 31;
    const int warp = tid >> 5;
    const int g    = lane >> 2;    // 0..7
    const int tc   = lane & 3;     // 0..3
    const int m0   = warp * 16;    // token tile base

    // ---- constants ----
    for (int i = tid; i < 48 * 64; i += 256) {
        int r = i >> 6, d = i & 63;
        float v = (r < 32) ? Wq[i] : ((r == 32) ? Wg[d] : 0.0f);
        sm[O_WQS + r * PW + d] = tf32r(v);
    }
    if (tid < SLOTS) {
        float a[ADIM]; float ss = 0.0f;
        #pragma unroll
        for (int k = 0; k < ADIM; k++) { a[k] = ma[tid * ADIM + k]; ss += a[k] * a[k]; }
        float r4 = 4.0f / fmaxf(sqrtf(ss), 1e-12f);
        #pragma unroll
        for (int k = 0; k < ADIM; k++)
            sm[O_AS + tid * PQ + k] = tf32r(a[k] * r4);
    }
    const float bgv = bg[0];

    // ---- per-lane ldmatrix address bases (bytes) ----
    const int l7  = lane & 7;
    const int lml = (lane >> 3) & 1;
    const int lmh = lane >> 4;
    const int lhi = lane >> 4;
    const int lcm = (lane >> 3) & 1;

    const int s0  = (warp & 3) * 16;   // P-GEMM slot tile
    const int ntb = (warp >> 2) * 4;   // P-GEMM e tile base (x8)

    const uint32_t aWW = sb + (uint32_t)(O_WWS + (s0 + l7 + 8 * lml) * PT + 4 * lmh) * 4;
    const uint32_t aQS = sb + (uint32_t)(O_QS  + (m0 + l7 + 8 * lml) * PQ + 4 * lmh) * 4;
    const uint32_t bAS = sb + (uint32_t)(O_AS  + (lhi * 8 + l7) * PQ + 4 * lcm) * 4;
    const uint32_t bWQ = sb + (uint32_t)(O_WQS + (lhi * 8 + l7) * PW + 4 * lcm) * 4;
    const int rowX0 = (ntb + 0 + lhi) * 8 + l7;
    const int rowX2 = (ntb + 2 + lhi) * 8 + l7;
    const uint32_t bX0 = sb + (uint32_t)(O_XTS + rowX0 * PT) * 4;
    const uint32_t bX2 = sb + (uint32_t)(O_XTS + rowX2 * PT) * 4;
    const uint32_t keyX0 = (rowX0 >> 2) & 7, keyX2 = (rowX2 >> 2) & 7;

    // persistent P accumulators
    float cp[4][4];
    #pragma unroll
    for (int j = 0; j < 4; j++)
        #pragma unroll
        for (int u = 0; u < 4; u++) cp[j][u] = 0.0f;
    float wsum = 0.0f;

    const int tA = m0 + g, tB = m0 + g + 8;
    const int cA = tA >> 2, wA = tA & 3, cB = tB >> 2, wB = tB & 3;

    for (int c = 0; c < NCHUNK; c++) {
        __syncthreads();   // previous chunk's readers of xts/wws done

        // ---- load x chunk -> swizzled x^T (tf32) ----
        const float4* xg = (const float4*)(x + ((size_t)b * TOKENS + (bx * NCHUNK + c) * TILE_T) * EDIM);
        #pragma unroll
        for (int k = 0; k < 8; k++) {
            int f = tid + k * 256;
            float4 v = xg[f];
            int t = f >> 4, d = (f & 15) * 4;
            sm[xidx(d + 0, t)] = tf32r(v.x);
            sm[xidx(d + 1, t)] = tf32r(v.y);
            sm[xidx(d + 2, t)] = tf32r(v.z);
            sm[xidx(d + 3, t)] = tf32r(v.w);
        }
        __syncthreads();

        // ============ Q-GEMM: C_q[16t x 40] = x @ [Wq;Wg]^T ============
        float cq[5][4];
        #pragma unroll
        for (int nt = 0; nt < 5; nt++)
            #pragma unroll
            for (int u = 0; u < 4; u++) cq[nt][u] = 0.0f;
        #pragma unroll
        for (int k = 0; k < 8; k++) {
            const int k8 = k * 8;
            const int d0 = k8 + tc, d1 = k8 + tc + 4;
            const int k0 = (k8 >> 2) & 7, k1 = ((k8 >> 2) + 1) & 7;
            uint32_t a0 = U(sm[O_XTS + d0 * PT + (((cA ^ k0) << 2) | wA)]);
            uint32_t a1 = U(sm[O_XTS + d0 * PT + (((cB ^ k0) << 2) | wB)]);
            uint32_t a2 = U(sm[O_XTS + d1 * PT + (((cA ^ k1) << 2) | wA)]);
            uint32_t a3 = U(sm[O_XTS + d1 * PT + (((cB ^ k1) << 2) | wB)]);
            uint32_t bq0[4], bq1[4], bq2[4];
            ldm4(bq0, bWQ + (uint32_t)(k8 * 4));
            ldm4(bq1, bWQ + (uint32_t)(2 * 8 * PW * 4 + k8 * 4));
            ldm4(bq2, bWQ + (uint32_t)(4 * 8 * PW * 4 + k8 * 4));
            mma8(cq[0], a0, a1, a2, a3, bq0[0], bq0[1]);
            mma8(cq[1], a0, a1, a2, a3, bq0[2], bq0[3]);
            mma8(cq[2], a0, a1, a2, a3, bq1[0], bq1[1]);
            mma8(cq[3], a0, a1, a2, a3, bq1[2], bq1[3]);
            mma8(cq[4], a0, a1, a2, a3, bq2[0], bq2[1]);
        }
        // norms (cols 0-31) + gate (col 32)
        float ss0 = 0.f, ss1 = 0.f;
        #pragma unroll
        for (int nt = 0; nt < 4; nt++) {
            ss0 += cq[nt][0] * cq[nt][0] + cq[nt][1] * cq[nt][1];
            ss1 += cq[nt][2] * cq[nt][2] + cq[nt][3] * cq[nt][3];
        }
        ss0 += __shfl_xor_sync(0xffffffffu, ss0, 1);
        ss0 += __shfl_xor_sync(0xffffffffu, ss0, 2);
        ss1 += __shfl_xor_sync(0xffffffffu, ss1, 1);
        ss1 += __shfl_xor_sync(0xffffffffu, ss1, 2);
        const float rs0 = 1.0f / fmaxf(sqrtf(ss0), 1e-12f);
        const float rs1 = 1.0f / fmaxf(sqrtf(ss1), 1e-12f);
        const float gl0 = __shfl_sync(0xffffffffu, cq[4][0], lane & ~3);
        const float gl1 = __shfl_sync(0xffffffffu, cq[4][2], lane & ~3);
        const float gate0 = 1.0f / (1.0f + __expf(-(gl0 + bgv)));
        const float gate1 = 1.0f / (1.0f + __expf(-(gl1 + bgv)));
        #pragma unroll
        for (int nt = 0; nt < 4; nt++) {
            const int col = nt * 8 + 2 * tc;
            sm[O_QS + tA * PQ + col]     = tf32r(cq[nt][0] * rs0);
            sm[O_QS + tA * PQ + col + 1] = tf32r(cq[nt][1] * rs0);
            sm[O_QS + tB * PQ + col]     = tf32r(cq[nt][2] * rs1);
            sm[O_QS + tB * PQ + col + 1] = tf32r(cq[nt][3] * rs1);
        }
        __syncwarp();

        // ============ S-GEMM: C_s[16t x 64s] = qhat @ (4*ahat)^T ============
        float cs[8][4];
        #pragma unroll
        for (int nt = 0; nt < 8; nt++)
            #pragma unroll
            for (int u = 0; u < 4; u++) cs[nt][u] = 0.0f;
        #pragma unroll
        for (int k = 0; k < 4; k++) {
            const int k8 = k * 8;
            uint32_t aq[4];
            ldm4(aq, aQS + (uint32_t)(k8 * 4));
            #pragma unroll
            for (int jp = 0; jp < 4; jp++) {
                uint32_t bs[4];
                ldm4(bs, bAS + (uint32_t)(jp * 2 * 8 * PQ * 4 + k8 * 4));
                mma8(cs[jp * 2],     aq[0], aq[1], aq[2], aq[3], bs[0], bs[1]);
                mma8(cs[jp * 2 + 1], aq[0], aq[1], aq[2], aq[3], bs[2], bs[3]);
            }
        }
        // softmax (scores in [-4,4]; no max-subtract)
        float z0 = 0.f, z1 = 0.f;
        #pragma unroll
        for (int nt = 0; nt < 8; nt++) {
            cs[nt][0] = __expf(cs[nt][0]); z0 += cs[nt][0];
            cs[nt][1] = __expf(cs[nt][1]); z0 += cs[nt][1];
            cs[nt][2] = __expf(cs[nt][2]); z1 += cs[nt][2];
            cs[nt][3] = __expf(cs[nt][3]); z1 += cs[nt][3];
        }
        z0 += __shfl_xor_sync(0xffffffffu, z0, 1);
        z0 += __shfl_xor_sync(0xffffffffu, z0, 2);
        z1 += __shfl_xor_sync(0xffffffffu, z1, 1);
        z1 += __shfl_xor_sync(0xffffffffu, z1, 2);
        const float k0 = gate0 / z0, k1 = gate1 / z1;
        #pragma unroll
        for (int nt = 0; nt < 8; nt++) {
            const int s = nt * 8 + 2 * tc;
            sm[O_WWS + s       * PT + tA] = tf32r(cs[nt][0] * k0);
            sm[O_WWS + (s + 1) * PT + tA] = tf32r(cs[nt][1] * k0);
            sm[O_WWS + s       * PT + tB] = tf32r(cs[nt][2] * k1);
            sm[O_WWS + (s + 1) * PT + tB] = tf32r(cs[nt][3] * k1);
        }
        __syncthreads();

        // ---- W partial sums (threads 0..63) ----
        if (tid < SLOTS) {
            const float2* wr = (const float2*)&sm[O_WWS + tid * PT];
            float s = 0.f;
            #pragma unroll 16
            for (int t2 = 0; t2 < TILE_T / 2; t2++) { float2 v = wr[t2]; s += v.x + v.y; }
            wsum += s;
        }

        // ============ P-GEMM: cp[16s x 32e] += ww^T @ x ============
        #pragma unroll
        for (int k = 0; k < 16; k++) {
            const int k8 = k * 8;
            uint32_t ap[4], b0[4], b1[4];
            ldm4(ap, aWW + (uint32_t)(k8 * 4));
            const uint32_t ch = (uint32_t)((k8 >> 2) + lcm);
            ldm4(b0, bX0 + ((ch ^ keyX0) << 4));
            ldm4(b1, bX2 + ((ch ^ keyX2) << 4));
            mma8(cp[0], ap[0], ap[1], ap[2], ap[3], b0[0], b0[1]);
            mma8(cp[1], ap[0], ap[1], ap[2], ap[3], b0[2], b0[3]);
            mma8(cp[2], ap[0], ap[1], ap[2], ap[3], b1[0], b1[1]);
            mma8(cp[3], ap[0], ap[1], ap[2], ap[3], b1[2], b1[3]);
        }
    }

    // ---- flush partials (exclusive slices) ----
    float* dst = &g_Ppart[((size_t)(bx * BATCH + b)) * SLOTS * EDIM];
    #pragma unroll
    for (int j = 0; j < 4; j++) {
        const int e = (ntb + j) * 8 + 2 * tc;
        dst[(s0 + g)     * EDIM + e]     = cp[j][0];
        dst[(s0 + g)     * EDIM + e + 1] = cp[j][1];
        dst[(s0 + g + 8) * EDIM + e]     = cp[j][2];
        dst[(s0 + g + 8) * EDIM + e + 1] = cp[j][3];
    }
    if (tid < SLOTS) g_Wpart[(bx * BATCH + b) * SLOTS + tid] = wsum;
}

// ============================================================
// finalize: grid (BATCH, 4), each block = 16 slots of one batch
// 256 CTAs -> ~14 warps/SM of latency-hiding (was 128 CTAs / 7 warps)
// ============================================================
#define FP 20   // Pt row pad (16 slots + 4)
__global__ __launch_bounds__(256)
void finalize_kernel(const float* __restrict__ mv,
                     const float* __restrict__ Wv,
                     float* __restrict__ out)
{
    __shared__ float Pt [EDIM * FP];    // Pt[d][s'] 16+pad
    __shared__ float WvT[EDIM * 68];    // WvT[d][e]
    __shared__ float wsh[16];

    const int b  = blockIdx.x;
    const int qB = blockIdx.y;          // slot quarter
    const int sB = qB * 16;
    const int tid = threadIdx.x;

    // load P partials for 16 slots (sum over BPB), coalesced over d
    for (int i = tid; i < 16 * EDIM; i += 256) {
        const int sp = i >> 6, d = i & 63;
        float p = 0.f;
        #pragma unroll
        for (int k = 0; k < BPB; k++)
            p += g_Ppart[((size_t)(k * BATCH + b)) * SLOTS * EDIM + (sB + sp) * EDIM + d];
        Pt[d * FP + sp] = p;
    }
    // Wv transposed (L2-hot, shared across 256 blocks)
    for (int i = tid; i < EDIM * EDIM; i += 256) {
        const int e = i >> 6, d = i & 63;
        WvT[d * 68 + e] = Wv[i];
    }
    if (tid < 16) {
        float w = 0.f;
        #pragma unroll
        for (int k = 0; k < BPB; k++)
            w += g_Wpart[(k * BATCH + b) * SLOTS + sB + tid];
        wsh[tid] = w;
    }
    __syncthreads();

    const int sp = tid >> 4;            // 0..15 -> slot
    const int tx = tid & 15;            // 0..15 -> 4 e each
    float acc[4] = {0.f, 0.f, 0.f, 0.f};

    #pragma unroll 8
    for (int d = 0; d < EDIM; d++) {
        const float pv = Pt[d * FP + sp];
        const float4 w4 = *(const float4*)&WvT[d * 68 + tx * 4];
        acc[0] += pv * w4.x; acc[1] += pv * w4.y;
        acc[2] += pv * w4.z; acc[3] += pv * w4.w;
    }

    const int s = sB + sp;
    const float W  = wsh[sp];
    const float em = __expf(-W);                      // 1-g
    const float sc = (1.0f - em) / fmaxf(W, 1e-6f);   // g/max(W,1e-6)
    const float4 m4 = ((const float4*)mv)[((size_t)b * SLOTS + s) * 16 + tx];
    float4 o;
    o.x = m4.x * em + acc[0] * sc;
    o.y = m4.y * em + acc[1] * sc;
    o.z = m4.z * em + acc[2] * sc;
    o.w = m4.w * em + acc[3] * sc;
    ((float4*)out)[((size_t)b * SLOTS + s) * 16 + tx] = o;
}

// ============================================================
extern "C" void kernel_launch(void* const* d_in, const int* in_sizes, int n_in,
                              void* d_out, int out_size) {
    const float* x  = (const float*)d_in[0];
    const float* ma = (const float*)d_in[1];
    const float* mv = (const float*)d_in[2];
    const float* Wq = (const float*)d_in[3];
    const float* Wv = (const float*)d_in[4];
    const float* Wg = (const float*)d_in[5];
    const float* bg = (const float*)d_in[6];
    float* out = (float*)d_out;
    (void)in_sizes; (void)n_in; (void)out_size;

    cudaFuncSetAttribute(main_kernel,
                         cudaFuncAttributeMaxDynamicSharedMemorySize, SM_BYTES);

    dim3 grid(BPB, BATCH);
    main_kernel<<<grid, 256, SM_BYTES>>>(x, ma, Wq, Wg, bg);
    dim3 fgrid(BATCH, 4);
    finalize_kernel<<<fgrid, 256>>>(mv, Wv, out);
}